// round 11
// baseline (speedup 1.0000x reference)
#include <cuda_runtime.h>
#include <cuda_fp16.h>
#include <cstdint>

// ---------------------------------------------------------------------------
// DCNv2 on GB300 (compute_103 PTX -> no tcgen05; fp16 mma.sync m16n8k16):
//   Stage P: pack weights -> g_wpack [1728, 1152] fp16 (vectorized)
//   Stage I: im2col x -> g_cols [32768, 1152] fp16
//   Stage G: fp16 mma.sync GEMM (fp32 accum), 3-stage cp.async pipeline,
//            CTA 64x128 (zero pad, fine-grain tail), 2 CTAs/SM,
//            fused bias/sigmoid -> g_conv fp16
//   Stage D: deformable gather, 1 px/thread, hoisted offset/mask loads
// ---------------------------------------------------------------------------

#define B_      2
#define C_      128
#define H_      256
#define W_      256
#define HO_     128
#define WO_     128
#define G_      64
#define OC_OFF  1152
#define OC_ALL  1728
#define KDIM    1152
#define NPIX    32768
#define MPAD    1792

__device__ __align__(1024) __half g_conv[(size_t)B_ * OC_ALL * HO_ * WO_];
__device__ __align__(1024) __half g_cols[(size_t)NPIX * KDIM];
__device__ __align__(1024) __half g_wpack[(size_t)MPAD * KDIM];

// ------------------------------- helpers ----------------------------------
__device__ __forceinline__ uint32_t smem_u32(const void* p) {
    uint32_t a;
    asm("{ .reg .u64 t; cvta.to.shared.u64 t, %1; cvt.u32.u64 %0, t; }" : "=r"(a) : "l"(p));
    return a;
}
#define CP_ASYNC16(dst, src) \
    asm volatile("cp.async.cg.shared.global [%0], [%1], 16;" :: "r"(dst), "l"(src) : "memory")
#define CP_COMMIT() asm volatile("cp.async.commit_group;" ::: "memory")
#define CP_WAIT(n)  asm volatile("cp.async.wait_group %0;" :: "n"(n) : "memory")

#define LDSM_X4(r0, r1, r2, r3, addr)                                          \
    asm volatile("ldmatrix.sync.aligned.m8n8.x4.shared.b16 {%0,%1,%2,%3}, [%4];" \
        : "=r"(r0), "=r"(r1), "=r"(r2), "=r"(r3) : "r"(addr))

#define MMA_F16(d, a, b)                                                       \
    asm volatile("mma.sync.aligned.m16n8k16.row.col.f32.f16.f16.f32 "          \
        "{%0,%1,%2,%3}, {%4,%5,%6,%7}, {%8,%9}, {%0,%1,%2,%3};"                \
        : "+f"((d)[0]), "+f"((d)[1]), "+f"((d)[2]), "+f"((d)[3])               \
        : "r"((a)[0]), "r"((a)[1]), "r"((a)[2]), "r"((a)[3]),                  \
          "r"((b)[0]), "r"((b)[1]))

// ---------------------------------------------------------------------------
// Stage P: pack weights -> fp16, 8 elems/thread (KDIM % 8 == 0).
// ---------------------------------------------------------------------------
__global__ __launch_bounds__(256)
void pack_w(const float* __restrict__ wo, const float* __restrict__ wm)
{
    const size_t i = ((size_t)blockIdx.x * 256 + threadIdx.x) * 8;
    if (i >= (size_t)OC_ALL * KDIM) return;
    const int row = (int)(i / KDIM);

    float4 a, c;
    if (row < OC_OFF) {
        a = *reinterpret_cast<const float4*>(wo + i);
        c = *reinterpret_cast<const float4*>(wo + i + 4);
    } else {
        const size_t j = i - (size_t)OC_OFF * KDIM;
        a = *reinterpret_cast<const float4*>(wm + j);
        c = *reinterpret_cast<const float4*>(wm + j + 4);
    }
    __half2 h0 = __floats2half2_rn(a.x, a.y);
    __half2 h1 = __floats2half2_rn(a.z, a.w);
    __half2 h2 = __floats2half2_rn(c.x, c.y);
    __half2 h3 = __floats2half2_rn(c.z, c.w);
    uint4 pk = make_uint4(*(uint32_t*)&h0, *(uint32_t*)&h1,
                          *(uint32_t*)&h2, *(uint32_t*)&h3);
    *reinterpret_cast<uint4*>(&g_wpack[i]) = pk;
}

// ---------------------------------------------------------------------------
// Stage I: im2col -> fp16, 8-byte vector stores.
// ---------------------------------------------------------------------------
__global__ __launch_bounds__(256)
void im2col_kernel(const float* __restrict__ x)
{
    __shared__ float st[32][73];
    const int t  = threadIdx.x;
    const int wl = t & 31;
    const int cl = t >> 5;
    const int n0 = blockIdx.x * 32;
    const int b  = n0 >> 14;
    const int ho = (n0 >> 7) & 127;
    const int wo = (n0 & 127) + wl;
    const int iy0 = 2 * ho - 1;
    const int ix0 = 2 * wo - 1;

    for (int cc = 0; cc < 16; ++cc) {
        const int c = cc * 8 + cl;
        const float* xp = x + (size_t)(b * C_ + c) * H_ * W_;
#pragma unroll
        for (int ky = 0; ky < 3; ++ky) {
            const int iy = iy0 + ky;
            const bool vy = (unsigned)iy < (unsigned)H_;
#pragma unroll
            for (int kx = 0; kx < 3; ++kx) {
                const int ix = ix0 + kx;
                float v = 0.f;
                if (vy && (unsigned)ix < (unsigned)W_) v = xp[iy * W_ + ix];
                st[wl][cl * 9 + ky * 3 + kx] = v;
            }
        }
        __syncthreads();
        for (int i = t; i < 32 * 18; i += 256) {
            const int r = i / 18, q = i - r * 18;
            const float* s = &st[r][q * 4];
            __half2 h01 = __floats2half2_rn(s[0], s[1]);
            __half2 h23 = __floats2half2_rn(s[2], s[3]);
            uint2 pk = make_uint2(*(uint32_t*)&h01, *(uint32_t*)&h23);
            *reinterpret_cast<uint2*>(
                &g_cols[(size_t)(n0 + r) * KDIM + cc * 72 + q * 4]) = pk;
        }
        __syncthreads();
    }
}

// ---------------------------------------------------------------------------
// Stage G: fp16 mma.sync GEMM. CTA 64x128, 128 thr (4 warps, warp 32x64),
// 2 CTAs/SM. M = 27 tiles exactly (no pad). KCH=64, 3-stage cp.async.
// ---------------------------------------------------------------------------
#define MT      64
#define NT      128
#define KCH     64
#define NKC     18
#define NSTG    3
#define LDP     72
#define ASF     (MT * LDP)      // 4608 halfs
#define BSF     (NT * LDP)      // 9216 halfs
#define STGH    (ASF + BSF)
#define STGB    (STGH * 2)      // 27648 B

__global__ __launch_bounds__(128, 2)
void gemm_f16(const float* __restrict__ b_off, const float* __restrict__ b_msk)
{
    extern __shared__ __half sm[];

    const int tid  = threadIdx.x;
    const int wid  = tid >> 5;
    const int lane = tid & 31;
    const int wm   = wid & 1;        // 2 warps in M (x32)
    const int wn   = wid >> 1;       // 2 warps in N (x64)
    const int lm   = lane >> 2;
    const int lk   = lane & 3;
    const int g    = lane >> 3;
    const int li   = lane & 7;
    const int ocb  = blockIdx.x * MT;
    const int nb   = blockIdx.y * NT;

    const __half* Abase = g_wpack + (size_t)ocb * KDIM;
    const __half* Bbase = g_cols + (size_t)nb * KDIM;
    const uint32_t smb = smem_u32(sm);

    const uint32_t aoff = (uint32_t)((wm * 32 + (g & 1) * 8 + li) * LDP + (g >> 1) * 8) * 2;
    const uint32_t boff = (uint32_t)(ASF + (wn * 64 + (g >> 1) * 8 + li) * LDP + (g & 1) * 8) * 2;

    float d[2][8][4];
#pragma unroll
    for (int t = 0; t < 2; ++t)
#pragma unroll
        for (int nt = 0; nt < 8; ++nt)
#pragma unroll
            for (int j = 0; j < 4; ++j) d[t][nt][j] = 0.f;

    // one stage: A 512 x 16B chunks + B 1024 x 16B chunks, 128 threads
    auto load_stage = [&](int kn) {
        const uint32_t stb = smb + (uint32_t)(kn % NSTG) * STGB;
        const __half* As = Abase + kn * KCH;
        const __half* Bs = Bbase + kn * KCH;
#pragma unroll
        for (int j = 0; j < 4; ++j) {
            const int i = tid + j * 128;
            const int r = i >> 3, c = i & 7;
            CP_ASYNC16(stb + (uint32_t)(r * LDP + c * 8) * 2,
                       As + (size_t)r * KDIM + c * 8);
        }
#pragma unroll
        for (int j = 0; j < 8; ++j) {
            const int i = tid + j * 128;
            const int r = i >> 3, c = i & 7;
            CP_ASYNC16(stb + (uint32_t)(ASF + r * LDP + c * 8) * 2,
                       Bs + (size_t)r * KDIM + c * 8);
        }
        CP_COMMIT();
    };

    load_stage(0);
    load_stage(1);

    for (int kc = 0; kc < NKC; ++kc) {
        CP_WAIT(1);
        __syncthreads();

        if (kc + 2 < NKC) load_stage(kc + 2);

        const uint32_t sb = smb + (uint32_t)(kc % NSTG) * STGB;

#pragma unroll
        for (int ks = 0; ks < 4; ++ks) {
            const uint32_t kb = (uint32_t)ks * 32;
            uint32_t a[2][4];
            LDSM_X4(a[0][0], a[0][1], a[0][2], a[0][3], sb + aoff + kb);
            LDSM_X4(a[1][0], a[1][1], a[1][2], a[1][3],
                    sb + aoff + 16 * LDP * 2 + kb);
            uint32_t bw[8][2];
#pragma unroll
            for (int np = 0; np < 4; ++np)
                LDSM_X4(bw[np * 2][0], bw[np * 2][1],
                        bw[np * 2 + 1][0], bw[np * 2 + 1][1],
                        sb + boff + (uint32_t)(np * 16 * LDP) * 2 + kb);
#pragma unroll
            for (int t = 0; t < 2; ++t)
#pragma unroll
                for (int nt = 0; nt < 8; ++nt)
                    MMA_F16(d[t][nt], a[t], bw[nt]);
        }
    }

    // ---- epilogue: bias (+sigmoid), fp16 __half2 coalesced stores ----
    const int b    = nb >> 14;
    const int pixb = nb & 16383;

#pragma unroll
    for (int t = 0; t < 2; ++t) {
        const int r0 = ocb + wm * 32 + t * 16 + lm;
#pragma unroll
        for (int half = 0; half < 2; ++half) {
            const int oc = r0 + half * 8;          // always < OC_ALL (27*64)
            const bool msk = (oc >= OC_OFF);
            const float bias = msk ? b_msk[oc - OC_OFF] : b_off[oc];
            __half* rowp = g_conv + ((size_t)b * OC_ALL + oc) * 16384 + pixb;
#pragma unroll
            for (int nt = 0; nt < 8; ++nt) {
                const int col = wn * 64 + nt * 8 + 2 * lk;
                float v0 = d[t][nt][2 * half + 0] + bias;
                float v1 = d[t][nt][2 * half + 1] + bias;
                if (msk) {
                    v0 = 1.f / (1.f + __expf(-v0));
                    v1 = 1.f / (1.f + __expf(-v1));
                }
                *reinterpret_cast<__half2*>(rowp + col) = __floats2half2_rn(v0, v1);
            }
        }
    }
}

// ---------------------------------------------------------------------------
// Stage D: deformable gather, 1 px/thread, hoisted offset/mask loads.
// (round-8 configuration — best measured)
// ---------------------------------------------------------------------------
__global__ __launch_bounds__(128)
void deform_kernel(const float* __restrict__ x,
                   const float* __restrict__ w_deform,
                   float* __restrict__ out)
{
    const int blk = blockIdx.x;
    const int ho  = blk & 127;
    const int g   = (blk >> 7) & 63;
    const int b   = blk >> 13;
    const int wo  = threadIdx.x;

    __shared__ float wd[2][2][9];
    if (threadIdx.x < 36) {
        const int o = threadIdx.x / 18;
        const int c = (threadIdx.x / 9) & 1;
        const int k = threadIdx.x % 9;
        wd[o][c][k] = w_deform[(((size_t)(g * 2 + o)) * 2 + c) * 9 + k];
    }
    __syncthreads();

    const size_t CS  = (size_t)HO_ * WO_;
    const size_t pix = (size_t)ho * WO_ + wo;
    const __half* cv_b = g_conv + (size_t)b * OC_ALL * CS + pix;

    __half dyv[9], dxv[9], mv[9];
    const int ch0 = g * 18;
#pragma unroll
    for (int k = 0; k < 9; ++k) {
        dyv[k] = cv_b[(size_t)(ch0 + 2 * k) * CS];
        dxv[k] = cv_b[(size_t)(ch0 + 2 * k + 1) * CS];
        mv[k]  = cv_b[(size_t)(OC_OFF + g * 9 + k) * CS];
    }

    const float* xg0 = x + ((size_t)(b * C_ + g * 2) * H_) * W_;
    const float* xg1 = xg0 + (size_t)H_ * W_;

    float acc0 = 0.f, acc1 = 0.f;

#pragma unroll
    for (int k = 0; k < 9; ++k) {
        const float dy = __half2float(dyv[k]);
        const float dx = __half2float(dxv[k]);
        const float m  = __half2float(mv[k]);

        const int ki = k / 3, kj = k - ki * 3;
        const float py = dy + (float)(2 * ho - 1 + ki);
        const float px = dx + (float)(2 * wo - 1 + kj);

        const float y0f = floorf(py), x0f = floorf(px);
        const float wy = py - y0f, wx = px - x0f;
        const int y0 = (int)y0f, x0 = (int)x0f;
        const int y1 = y0 + 1, x1 = x0 + 1;

        const bool vy0 = (unsigned)y0 < (unsigned)H_;
        const bool vy1 = (unsigned)y1 < (unsigned)H_;
        const bool vx0 = (unsigned)x0 < (unsigned)W_;
        const bool vx1 = (unsigned)x1 < (unsigned)W_;

        const float w00 = (1.f - wy) * (1.f - wx);
        const float w01 = (1.f - wy) * wx;
        const float w10 = wy * (1.f - wx);
        const float w11 = wy * wx;

        const int i00 = y0 * W_ + x0;
        const int i01 = y0 * W_ + x1;
        const int i10 = y1 * W_ + x0;
        const int i11 = y1 * W_ + x1;

        float s0 = 0.f, s1 = 0.f;
        if (vy0 && vx0) { s0 += w00 * xg0[i00]; s1 += w00 * xg1[i00]; }
        if (vy0 && vx1) { s0 += w01 * xg0[i01]; s1 += w01 * xg1[i01]; }
        if (vy1 && vx0) { s0 += w10 * xg0[i10]; s1 += w10 * xg1[i10]; }
        if (vy1 && vx1) { s0 += w11 * xg0[i11]; s1 += w11 * xg1[i11]; }

        s0 *= m; s1 *= m;
        acc0 = fmaf(s0, wd[0][0][k], acc0);
        acc0 = fmaf(s1, wd[0][1][k], acc0);
        acc1 = fmaf(s0, wd[1][0][k], acc1);
        acc1 = fmaf(s1, wd[1][1][k], acc1);
    }

    float* o0 = out + (((size_t)b * C_ + g * 2) * HO_ + ho) * WO_ + wo;
    o0[0]  = acc0;
    o0[CS] = acc1;
}

// ---------------------------------------------------------------------------
extern "C" void kernel_launch(void* const* d_in, const int* in_sizes, int n_in,
                              void* d_out, int out_size)
{
    const float* x        = (const float*)d_in[0];
    const float* w_offset = (const float*)d_in[1];
    const float* b_offset = (const float*)d_in[2];
    const float* w_mask   = (const float*)d_in[3];
    const float* b_mask   = (const float*)d_in[4];
    const float* w_deform = (const float*)d_in[5];
    float* out = (float*)d_out;

    const size_t wtot = (size_t)OC_ALL * KDIM;
    pack_w<<<(unsigned)((wtot / 8 + 255) / 256), 256>>>(w_offset, w_mask);

    im2col_kernel<<<NPIX / 32, 256>>>(x);

    const int smem = NSTG * STGB;   // 82944 B
    cudaFuncSetAttribute(gemm_f16, cudaFuncAttributeMaxDynamicSharedMemorySize, smem);
    gemm_f16<<<dim3(OC_ALL / MT, NPIX / NT), 128, smem>>>(b_offset, b_mask);

    deform_kernel<<<B_ * G_ * HO_, 128>>>(x, w_deform, out);
}

// round 13
// speedup vs baseline: 1.1409x; 1.1409x over previous
#include <cuda_runtime.h>
#include <cuda_fp16.h>
#include <cstdint>

// ---------------------------------------------------------------------------
// DCNv2 on GB300 (compute_103 PTX -> no tcgen05; fp16 mma.sync m16n8k16):
//   Stage P: pack weights -> g_wpack [1728(,+64 zero)] x 1152 fp16 (vectorized)
//   Stage I: im2col x -> g_cols [32768, 1152] fp16
//   Stage G: fp16 mma.sync GEMM (fp32 accum), 3-stage cp.async pipeline,
//            CTA 128x128, 2 CTAs/SM, pad-warp skip, fused bias/sigmoid
//   Stage D: deformable gather, 1 px/thread, hoisted offset/mask loads
// ---------------------------------------------------------------------------

#define B_      2
#define C_      128
#define H_      256
#define W_      256
#define HO_     128
#define WO_     128
#define G_      64
#define OC_OFF  1152
#define OC_ALL  1728
#define KDIM    1152
#define NPIX    32768
#define MPAD    1792

__device__ __align__(1024) __half g_conv[(size_t)B_ * OC_ALL * HO_ * WO_];
__device__ __align__(1024) __half g_cols[(size_t)NPIX * KDIM];
__device__ __align__(1024) __half g_wpack[(size_t)MPAD * KDIM];   // rows>=1728 stay 0

// ------------------------------- helpers ----------------------------------
__device__ __forceinline__ uint32_t smem_u32(const void* p) {
    uint32_t a;
    asm("{ .reg .u64 t; cvta.to.shared.u64 t, %1; cvt.u32.u64 %0, t; }" : "=r"(a) : "l"(p));
    return a;
}
#define CP_ASYNC16(dst, src) \
    asm volatile("cp.async.cg.shared.global [%0], [%1], 16;" :: "r"(dst), "l"(src) : "memory")
#define CP_COMMIT() asm volatile("cp.async.commit_group;" ::: "memory")
#define CP_WAIT(n)  asm volatile("cp.async.wait_group %0;" :: "n"(n) : "memory")

#define LDSM_X4(r0, r1, r2, r3, addr)                                          \
    asm volatile("ldmatrix.sync.aligned.m8n8.x4.shared.b16 {%0,%1,%2,%3}, [%4];" \
        : "=r"(r0), "=r"(r1), "=r"(r2), "=r"(r3) : "r"(addr))

#define MMA_F16(d, a, b)                                                       \
    asm volatile("mma.sync.aligned.m16n8k16.row.col.f32.f16.f16.f32 "          \
        "{%0,%1,%2,%3}, {%4,%5,%6,%7}, {%8,%9}, {%0,%1,%2,%3};"                \
        : "+f"((d)[0]), "+f"((d)[1]), "+f"((d)[2]), "+f"((d)[3])               \
        : "r"((a)[0]), "r"((a)[1]), "r"((a)[2]), "r"((a)[3]),                  \
          "r"((b)[0]), "r"((b)[1]))

// ---------------------------------------------------------------------------
// Stage P: pack weights -> fp16, 8 elems/thread (KDIM % 8 == 0).
// ---------------------------------------------------------------------------
__global__ __launch_bounds__(256)
void pack_w(const float* __restrict__ wo, const float* __restrict__ wm)
{
    const size_t i = ((size_t)blockIdx.x * 256 + threadIdx.x) * 8;
    if (i >= (size_t)OC_ALL * KDIM) return;
    const int row = (int)(i / KDIM);

    float4 a, c;
    if (row < OC_OFF) {
        a = *reinterpret_cast<const float4*>(wo + i);
        c = *reinterpret_cast<const float4*>(wo + i + 4);
    } else {
        const size_t j = i - (size_t)OC_OFF * KDIM;
        a = *reinterpret_cast<const float4*>(wm + j);
        c = *reinterpret_cast<const float4*>(wm + j + 4);
    }
    __half2 h0 = __floats2half2_rn(a.x, a.y);
    __half2 h1 = __floats2half2_rn(a.z, a.w);
    __half2 h2 = __floats2half2_rn(c.x, c.y);
    __half2 h3 = __floats2half2_rn(c.z, c.w);
    uint4 pk = make_uint4(*(uint32_t*)&h0, *(uint32_t*)&h1,
                          *(uint32_t*)&h2, *(uint32_t*)&h3);
    *reinterpret_cast<uint4*>(&g_wpack[i]) = pk;
}

// ---------------------------------------------------------------------------
// Stage I: im2col -> fp16, 8-byte vector stores.
// ---------------------------------------------------------------------------
__global__ __launch_bounds__(256)
void im2col_kernel(const float* __restrict__ x)
{
    __shared__ float st[32][73];
    const int t  = threadIdx.x;
    const int wl = t & 31;
    const int cl = t >> 5;
    const int n0 = blockIdx.x * 32;
    const int b  = n0 >> 14;
    const int ho = (n0 >> 7) & 127;
    const int wo = (n0 & 127) + wl;
    const int iy0 = 2 * ho - 1;
    const int ix0 = 2 * wo - 1;

    for (int cc = 0; cc < 16; ++cc) {
        const int c = cc * 8 + cl;
        const float* xp = x + (size_t)(b * C_ + c) * H_ * W_;
#pragma unroll
        for (int ky = 0; ky < 3; ++ky) {
            const int iy = iy0 + ky;
            const bool vy = (unsigned)iy < (unsigned)H_;
#pragma unroll
            for (int kx = 0; kx < 3; ++kx) {
                const int ix = ix0 + kx;
                float v = 0.f;
                if (vy && (unsigned)ix < (unsigned)W_) v = xp[iy * W_ + ix];
                st[wl][cl * 9 + ky * 3 + kx] = v;
            }
        }
        __syncthreads();
        for (int i = t; i < 32 * 18; i += 256) {
            const int r = i / 18, q = i - r * 18;
            const float* s = &st[r][q * 4];
            __half2 h01 = __floats2half2_rn(s[0], s[1]);
            __half2 h23 = __floats2half2_rn(s[2], s[3]);
            uint2 pk = make_uint2(*(uint32_t*)&h01, *(uint32_t*)&h23);
            *reinterpret_cast<uint2*>(
                &g_cols[(size_t)(n0 + r) * KDIM + cc * 72 + q * 4]) = pk;
        }
        __syncthreads();
    }
}

// ---------------------------------------------------------------------------
// Stage G: fp16 mma.sync GEMM. CTA 128x128, 256 thr (8 warps, warp 32x64),
// 2 CTAs/SM. KCH=64 halfs, 3-stage cp.async, one sync/iter.
// Last M tile: warps whose 32 rows are all padding skip LDSM+MMA.
// ---------------------------------------------------------------------------
#define MT      128
#define NT      128
#define KCH     64
#define NKC     18
#define NSTG    3
#define LDP     72
#define ASF     (MT * LDP)
#define BSF     (NT * LDP)
#define STGH    (ASF + BSF)
#define STGB    (STGH * 2)      // 36864 B

__global__ __launch_bounds__(256, 2)
void gemm_f16(const float* __restrict__ b_off, const float* __restrict__ b_msk)
{
    extern __shared__ __half sm[];

    const int tid  = threadIdx.x;
    const int wid  = tid >> 5;
    const int lane = tid & 31;
    const int wm   = wid & 3;
    const int wn   = wid >> 2;
    const int lm   = lane >> 2;
    const int lk   = lane & 3;
    const int g    = lane >> 3;
    const int li   = lane & 7;
    const int ocb  = blockIdx.x * MT;
    const int nb   = blockIdx.y * NT;

    // warp computes rows ocb + wm*32 .. +31; skip MMA entirely if all padding
    const bool mma_active = (ocb + wm * 32) < OC_ALL;

    const __half* Abase = g_wpack + (size_t)ocb * KDIM;
    const __half* Bbase = g_cols + (size_t)nb * KDIM;
    const uint32_t smb = smem_u32(sm);

    const uint32_t aoff = (uint32_t)((wm * 32 + (g & 1) * 8 + li) * LDP + (g >> 1) * 8) * 2;
    const uint32_t boff = (uint32_t)(ASF + (wn * 64 + (g >> 1) * 8 + li) * LDP + (g & 1) * 8) * 2;

    float d[2][8][4];
#pragma unroll
    for (int t = 0; t < 2; ++t)
#pragma unroll
        for (int nt = 0; nt < 8; ++nt)
#pragma unroll
            for (int j = 0; j < 4; ++j) d[t][nt][j] = 0.f;

    auto load_stage = [&](int kn) {
        const uint32_t stb = smb + (uint32_t)(kn % NSTG) * STGB;
        const __half* As = Abase + kn * KCH;
        const __half* Bs = Bbase + kn * KCH;
#pragma unroll
        for (int j = 0; j < 4; ++j) {
            const int i = tid + j * 256;
            const int r = i >> 3, c = i & 7;
            CP_ASYNC16(stb + (uint32_t)(r * LDP + c * 8) * 2,
                       As + (size_t)r * KDIM + c * 8);
        }
#pragma unroll
        for (int j = 0; j < 4; ++j) {
            const int i = tid + j * 256;
            const int r = i >> 3, c = i & 7;
            CP_ASYNC16(stb + (uint32_t)(ASF + r * LDP + c * 8) * 2,
                       Bs + (size_t)r * KDIM + c * 8);
        }
        CP_COMMIT();
    };

    load_stage(0);
    load_stage(1);

    for (int kc = 0; kc < NKC; ++kc) {
        CP_WAIT(1);
        __syncthreads();

        if (kc + 2 < NKC) load_stage(kc + 2);

        if (mma_active) {
            const uint32_t sb = smb + (uint32_t)(kc % NSTG) * STGB;
#pragma unroll
            for (int ks = 0; ks < 4; ++ks) {
                const uint32_t kb = (uint32_t)ks * 32;
                uint32_t a[2][4];
                LDSM_X4(a[0][0], a[0][1], a[0][2], a[0][3], sb + aoff + kb);
                LDSM_X4(a[1][0], a[1][1], a[1][2], a[1][3],
                        sb + aoff + 16 * LDP * 2 + kb);
                uint32_t bw[8][2];
#pragma unroll
                for (int np = 0; np < 4; ++np)
                    LDSM_X4(bw[np * 2][0], bw[np * 2][1],
                            bw[np * 2 + 1][0], bw[np * 2 + 1][1],
                            sb + boff + (uint32_t)(np * 16 * LDP) * 2 + kb);
#pragma unroll
                for (int t = 0; t < 2; ++t)
#pragma unroll
                    for (int nt = 0; nt < 8; ++nt)
                        MMA_F16(d[t][nt], a[t], bw[nt]);
            }
        }
    }

    // ---- epilogue: bias (+sigmoid), fp16 __half2 coalesced stores ----
    const int b    = nb >> 14;
    const int pixb = nb & 16383;

#pragma unroll
    for (int t = 0; t < 2; ++t) {
        const int r0 = ocb + wm * 32 + t * 16 + lm;
#pragma unroll
        for (int half = 0; half < 2; ++half) {
            const int oc = r0 + half * 8;
            if (oc >= OC_ALL) continue;
            const bool msk = (oc >= OC_OFF);
            const float bias = msk ? b_msk[oc - OC_OFF] : b_off[oc];
            __half* rowp = g_conv + ((size_t)b * OC_ALL + oc) * 16384 + pixb;
#pragma unroll
            for (int nt = 0; nt < 8; ++nt) {
                const int col = wn * 64 + nt * 8 + 2 * lk;
                float v0 = d[t][nt][2 * half + 0] + bias;
                float v1 = d[t][nt][2 * half + 1] + bias;
                if (msk) {
                    v0 = 1.f / (1.f + __expf(-v0));
                    v1 = 1.f / (1.f + __expf(-v1));
                }
                *reinterpret_cast<__half2*>(rowp + col) = __floats2half2_rn(v0, v1);
            }
        }
    }
}

// ---------------------------------------------------------------------------
// Stage D: deformable gather, 1 px/thread, hoisted offset/mask loads.
// ---------------------------------------------------------------------------
__global__ __launch_bounds__(128)
void deform_kernel(const float* __restrict__ x,
                   const float* __restrict__ w_deform,
                   float* __restrict__ out)
{
    const int blk = blockIdx.x;
    const int ho  = blk & 127;
    const int g   = (blk >> 7) & 63;
    const int b   = blk >> 13;
    const int wo  = threadIdx.x;

    __shared__ float wd[2][2][9];
    if (threadIdx.x < 36) {
        const int o = threadIdx.x / 18;
        const int c = (threadIdx.x / 9) & 1;
        const int k = threadIdx.x % 9;
        wd[o][c][k] = w_deform[(((size_t)(g * 2 + o)) * 2 + c) * 9 + k];
    }
    __syncthreads();

    const size_t CS  = (size_t)HO_ * WO_;
    const size_t pix = (size_t)ho * WO_ + wo;
    const __half* cv_b = g_conv + (size_t)b * OC_ALL * CS + pix;

    __half dyv[9], dxv[9], mv[9];
    const int ch0 = g * 18;
#pragma unroll
    for (int k = 0; k < 9; ++k) {
        dyv[k] = cv_b[(size_t)(ch0 + 2 * k) * CS];
        dxv[k] = cv_b[(size_t)(ch0 + 2 * k + 1) * CS];
        mv[k]  = cv_b[(size_t)(OC_OFF + g * 9 + k) * CS];
    }

    const float* xg0 = x + ((size_t)(b * C_ + g * 2) * H_) * W_;
    const float* xg1 = xg0 + (size_t)H_ * W_;

    float acc0 = 0.f, acc1 = 0.f;

#pragma unroll
    for (int k = 0; k < 9; ++k) {
        const float dy = __half2float(dyv[k]);
        const float dx = __half2float(dxv[k]);
        const float m  = __half2float(mv[k]);

        const int ki = k / 3, kj = k - ki * 3;
        const float py = dy + (float)(2 * ho - 1 + ki);
        const float px = dx + (float)(2 * wo - 1 + kj);

        const float y0f = floorf(py), x0f = floorf(px);
        const float wy = py - y0f, wx = px - x0f;
        const int y0 = (int)y0f, x0 = (int)x0f;
        const int y1 = y0 + 1, x1 = x0 + 1;

        const bool vy0 = (unsigned)y0 < (unsigned)H_;
        const bool vy1 = (unsigned)y1 < (unsigned)H_;
        const bool vx0 = (unsigned)x0 < (unsigned)W_;
        const bool vx1 = (unsigned)x1 < (unsigned)W_;

        const float w00 = (1.f - wy) * (1.f - wx);
        const float w01 = (1.f - wy) * wx;
        const float w10 = wy * (1.f - wx);
        const float w11 = wy * wx;

        const int i00 = y0 * W_ + x0;
        const int i01 = y0 * W_ + x1;
        const int i10 = y1 * W_ + x0;
        const int i11 = y1 * W_ + x1;

        float s0 = 0.f, s1 = 0.f;
        if (vy0 && vx0) { s0 += w00 * xg0[i00]; s1 += w00 * xg1[i00]; }
        if (vy0 && vx1) { s0 += w01 * xg0[i01]; s1 += w01 * xg1[i01]; }
        if (vy1 && vx0) { s0 += w10 * xg0[i10]; s1 += w10 * xg1[i10]; }
        if (vy1 && vx1) { s0 += w11 * xg0[i11]; s1 += w11 * xg1[i11]; }

        s0 *= m; s1 *= m;
        acc0 = fmaf(s0, wd[0][0][k], acc0);
        acc0 = fmaf(s1, wd[0][1][k], acc0);
        acc1 = fmaf(s0, wd[1][0][k], acc1);
        acc1 = fmaf(s1, wd[1][1][k], acc1);
    }

    float* o0 = out + (((size_t)b * C_ + g * 2) * HO_ + ho) * WO_ + wo;
    o0[0]  = acc0;
    o0[CS] = acc1;
}

// ---------------------------------------------------------------------------
extern "C" void kernel_launch(void* const* d_in, const int* in_sizes, int n_in,
                              void* d_out, int out_size)
{
    const float* x        = (const float*)d_in[0];
    const float* w_offset = (const float*)d_in[1];
    const float* b_offset = (const float*)d_in[2];
    const float* w_mask   = (const float*)d_in[3];
    const float* b_mask   = (const float*)d_in[4];
    const float* w_deform = (const float*)d_in[5];
    float* out = (float*)d_out;

    const size_t wtot = (size_t)OC_ALL * KDIM;
    pack_w<<<(unsigned)((wtot / 8 + 255) / 256), 256>>>(w_offset, w_mask);

    im2col_kernel<<<NPIX / 32, 256>>>(x);

    const int smem = NSTG * STGB;   // 110592 B
    cudaFuncSetAttribute(gemm_f16, cudaFuncAttributeMaxDynamicSharedMemorySize, smem);
    gemm_f16<<<dim3(MPAD / MT, NPIX / NT), 256, smem>>>(b_offset, b_mask);

    deform_kernel<<<B_ * G_ * HO_, 128>>>(x, w_deform, out);
}

// round 16
// speedup vs baseline: 1.1418x; 1.0008x over previous
#include <cuda_runtime.h>
#include <cuda_fp16.h>
#include <cstdint>

// ---------------------------------------------------------------------------
// DCNv2 on GB300 (compute_103 PTX -> no tcgen05; fp16 mma.sync m16n8k16):
//   Stage P+I (one launch): pack weights -> g_wpack fp16 (vectorized)
//                           + im2col x -> g_cols [32768, 1152] fp16
//   Stage G: fp16 mma.sync GEMM (fp32 accum), 3-stage cp.async pipeline,
//            CTA 128x128, 2 CTAs/SM, pad-warp skip, fused bias/sigmoid
//   Stage D: deformable gather; block-cooperative SMEM staging of the
//            27 offset/mask channels, 1 px/thread gathers
// ---------------------------------------------------------------------------

#define B_      2
#define C_      128
#define H_      256
#define W_      256
#define HO_     128
#define WO_     128
#define G_      64
#define OC_OFF  1152
#define OC_ALL  1728
#define KDIM    1152
#define NPIX    32768
#define MPAD    1792

#define I2C_BLOCKS  (NPIX / 32)                            // 1024
#define PACKW_ELEMS ((size_t)OC_ALL * KDIM)                // 1990656
#define PACKW_BLOCKS ((unsigned)((PACKW_ELEMS / 8 + 255) / 256))   // 972

__device__ __align__(1024) __half g_conv[(size_t)B_ * OC_ALL * HO_ * WO_];
__device__ __align__(1024) __half g_cols[(size_t)NPIX * KDIM];
__device__ __align__(1024) __half g_wpack[(size_t)MPAD * KDIM];   // rows>=1728 stay 0

// ------------------------------- helpers ----------------------------------
__device__ __forceinline__ uint32_t smem_u32(const void* p) {
    uint32_t a;
    asm("{ .reg .u64 t; cvta.to.shared.u64 t, %1; cvt.u32.u64 %0, t; }" : "=r"(a) : "l"(p));
    return a;
}
#define CP_ASYNC16(dst, src) \
    asm volatile("cp.async.cg.shared.global [%0], [%1], 16;" :: "r"(dst), "l"(src) : "memory")
#define CP_COMMIT() asm volatile("cp.async.commit_group;" ::: "memory")
#define CP_WAIT(n)  asm volatile("cp.async.wait_group %0;" :: "n"(n) : "memory")

#define LDSM_X4(r0, r1, r2, r3, addr)                                          \
    asm volatile("ldmatrix.sync.aligned.m8n8.x4.shared.b16 {%0,%1,%2,%3}, [%4];" \
        : "=r"(r0), "=r"(r1), "=r"(r2), "=r"(r3) : "r"(addr))

#define MMA_F16(d, a, b)                                                       \
    asm volatile("mma.sync.aligned.m16n8k16.row.col.f32.f16.f16.f32 "          \
        "{%0,%1,%2,%3}, {%4,%5,%6,%7}, {%8,%9}, {%0,%1,%2,%3};"                \
        : "+f"((d)[0]), "+f"((d)[1]), "+f"((d)[2]), "+f"((d)[3])               \
        : "r"((a)[0]), "r"((a)[1]), "r"((a)[2]), "r"((a)[3]),                  \
          "r"((b)[0]), "r"((b)[1]))

// ---------------------------------------------------------------------------
// Stage P+I fused: blocks [0, I2C_BLOCKS) do im2col; the rest pack weights.
// ---------------------------------------------------------------------------
__global__ __launch_bounds__(256)
void prep_kernel(const float* __restrict__ x,
                 const float* __restrict__ wo, const float* __restrict__ wm)
{
    if (blockIdx.x >= I2C_BLOCKS) {
        // ---- pack weights -> fp16, 8 elems/thread ----
        const size_t i =
            (((size_t)(blockIdx.x - I2C_BLOCKS)) * 256 + threadIdx.x) * 8;
        if (i >= PACKW_ELEMS) return;
        const int row = (int)(i / KDIM);
        float4 a, c;
        if (row < OC_OFF) {
            a = *reinterpret_cast<const float4*>(wo + i);
            c = *reinterpret_cast<const float4*>(wo + i + 4);
        } else {
            const size_t j = i - (size_t)OC_OFF * KDIM;
            a = *reinterpret_cast<const float4*>(wm + j);
            c = *reinterpret_cast<const float4*>(wm + j + 4);
        }
        __half2 h0 = __floats2half2_rn(a.x, a.y);
        __half2 h1 = __floats2half2_rn(a.z, a.w);
        __half2 h2 = __floats2half2_rn(c.x, c.y);
        __half2 h3 = __floats2half2_rn(c.z, c.w);
        uint4 pk = make_uint4(*(uint32_t*)&h0, *(uint32_t*)&h1,
                              *(uint32_t*)&h2, *(uint32_t*)&h3);
        *reinterpret_cast<uint4*>(&g_wpack[i]) = pk;
        return;
    }

    // ---- im2col -> fp16, 8-byte vector stores ----
    __shared__ float st[32][73];
    const int t  = threadIdx.x;
    const int wl = t & 31;
    const int cl = t >> 5;
    const int n0 = blockIdx.x * 32;
    const int b  = n0 >> 14;
    const int ho = (n0 >> 7) & 127;
    const int wo2 = (n0 & 127) + wl;
    const int iy0 = 2 * ho - 1;
    const int ix0 = 2 * wo2 - 1;

    for (int cc = 0; cc < 16; ++cc) {
        const int c = cc * 8 + cl;
        const float* xp = x + (size_t)(b * C_ + c) * H_ * W_;
#pragma unroll
        for (int ky = 0; ky < 3; ++ky) {
            const int iy = iy0 + ky;
            const bool vy = (unsigned)iy < (unsigned)H_;
#pragma unroll
            for (int kx = 0; kx < 3; ++kx) {
                const int ix = ix0 + kx;
                float v = 0.f;
                if (vy && (unsigned)ix < (unsigned)W_) v = xp[iy * W_ + ix];
                st[wl][cl * 9 + ky * 3 + kx] = v;
            }
        }
        __syncthreads();
        for (int i = t; i < 32 * 18; i += 256) {
            const int r = i / 18, q = i - r * 18;
            const float* s = &st[r][q * 4];
            __half2 h01 = __floats2half2_rn(s[0], s[1]);
            __half2 h23 = __floats2half2_rn(s[2], s[3]);
            uint2 pk = make_uint2(*(uint32_t*)&h01, *(uint32_t*)&h23);
            *reinterpret_cast<uint2*>(
                &g_cols[(size_t)(n0 + r) * KDIM + cc * 72 + q * 4]) = pk;
        }
        __syncthreads();
    }
}

// ---------------------------------------------------------------------------
// Stage G: fp16 mma.sync GEMM. CTA 128x128, 256 thr (8 warps, warp 32x64),
// 2 CTAs/SM. KCH=64 halfs, 3-stage cp.async, one sync/iter, pad-warp skip.
// ---------------------------------------------------------------------------
#define MT      128
#define NT      128
#define KCH     64
#define NKC     18
#define NSTG    3
#define LDP     72
#define ASF     (MT * LDP)
#define BSF     (NT * LDP)
#define STGH    (ASF + BSF)
#define STGB    (STGH * 2)      // 36864 B

__global__ __launch_bounds__(256, 2)
void gemm_f16(const float* __restrict__ b_off, const float* __restrict__ b_msk)
{
    extern __shared__ __half sm[];

    const int tid  = threadIdx.x;
    const int wid  = tid >> 5;
    const int lane = tid & 31;
    const int wm   = wid & 3;
    const int wn   = wid >> 2;
    const int lm   = lane >> 2;
    const int lk   = lane & 3;
    const int g    = lane >> 3;
    const int li   = lane & 7;
    const int ocb  = blockIdx.x * MT;
    const int nb   = blockIdx.y * NT;

    const bool mma_active = (ocb + wm * 32) < OC_ALL;

    const __half* Abase = g_wpack + (size_t)ocb * KDIM;
    const __half* Bbase = g_cols + (size_t)nb * KDIM;
    const uint32_t smb = smem_u32(sm);

    const uint32_t aoff = (uint32_t)((wm * 32 + (g & 1) * 8 + li) * LDP + (g >> 1) * 8) * 2;
    const uint32_t boff = (uint32_t)(ASF + (wn * 64 + (g >> 1) * 8 + li) * LDP + (g & 1) * 8) * 2;

    float d[2][8][4];
#pragma unroll
    for (int t = 0; t < 2; ++t)
#pragma unroll
        for (int nt = 0; nt < 8; ++nt)
#pragma unroll
            for (int j = 0; j < 4; ++j) d[t][nt][j] = 0.f;

    auto load_stage = [&](int kn) {
        const uint32_t stb = smb + (uint32_t)(kn % NSTG) * STGB;
        const __half* As = Abase + kn * KCH;
        const __half* Bs = Bbase + kn * KCH;
#pragma unroll
        for (int j = 0; j < 4; ++j) {
            const int i = tid + j * 256;
            const int r = i >> 3, c = i & 7;
            CP_ASYNC16(stb + (uint32_t)(r * LDP + c * 8) * 2,
                       As + (size_t)r * KDIM + c * 8);
        }
#pragma unroll
        for (int j = 0; j < 4; ++j) {
            const int i = tid + j * 256;
            const int r = i >> 3, c = i & 7;
            CP_ASYNC16(stb + (uint32_t)(ASF + r * LDP + c * 8) * 2,
                       Bs + (size_t)r * KDIM + c * 8);
        }
        CP_COMMIT();
    };

    load_stage(0);
    load_stage(1);

    for (int kc = 0; kc < NKC; ++kc) {
        CP_WAIT(1);
        __syncthreads();

        if (kc + 2 < NKC) load_stage(kc + 2);

        if (mma_active) {
            const uint32_t sb = smb + (uint32_t)(kc % NSTG) * STGB;
#pragma unroll
            for (int ks = 0; ks < 4; ++ks) {
                const uint32_t kb = (uint32_t)ks * 32;
                uint32_t a[2][4];
                LDSM_X4(a[0][0], a[0][1], a[0][2], a[0][3], sb + aoff + kb);
                LDSM_X4(a[1][0], a[1][1], a[1][2], a[1][3],
                        sb + aoff + 16 * LDP * 2 + kb);
                uint32_t bw[8][2];
#pragma unroll
                for (int np = 0; np < 4; ++np)
                    LDSM_X4(bw[np * 2][0], bw[np * 2][1],
                            bw[np * 2 + 1][0], bw[np * 2 + 1][1],
                            sb + boff + (uint32_t)(np * 16 * LDP) * 2 + kb);
#pragma unroll
                for (int t = 0; t < 2; ++t)
#pragma unroll
                    for (int nt = 0; nt < 8; ++nt)
                        MMA_F16(d[t][nt], a[t], bw[nt]);
            }
        }
    }

    // ---- epilogue: bias (+sigmoid), fp16 __half2 coalesced stores ----
    const int b    = nb >> 14;
    const int pixb = nb & 16383;

#pragma unroll
    for (int t = 0; t < 2; ++t) {
        const int r0 = ocb + wm * 32 + t * 16 + lm;
#pragma unroll
        for (int half = 0; half < 2; ++half) {
            const int oc = r0 + half * 8;
            if (oc >= OC_ALL) continue;
            const bool msk = (oc >= OC_OFF);
            const float bias = msk ? b_msk[oc - OC_OFF] : b_off[oc];
            __half* rowp = g_conv + ((size_t)b * OC_ALL + oc) * 16384 + pixb;
#pragma unroll
            for (int nt = 0; nt < 8; ++nt) {
                const int col = wn * 64 + nt * 8 + 2 * lk;
                float v0 = d[t][nt][2 * half + 0] + bias;
                float v1 = d[t][nt][2 * half + 1] + bias;
                if (msk) {
                    v0 = 1.f / (1.f + __expf(-v0));
                    v1 = 1.f / (1.f + __expf(-v1));
                }
                *reinterpret_cast<__half2*>(rowp + col) = __floats2half2_rn(v0, v1);
            }
        }
    }
}

// ---------------------------------------------------------------------------
// Stage D: deformable gather. Block = one (b, g, ho) row, 128 threads.
// The 27 offset/mask channels for this row are staged into SMEM with a
// block-cooperative coalesced load (27 x 256 B contiguous rows of g_conv).
// ---------------------------------------------------------------------------
__global__ __launch_bounds__(128)
void deform_kernel(const float* __restrict__ x,
                   const float* __restrict__ w_deform,
                   float* __restrict__ out)
{
    __shared__ __half cv[27][128];
    __shared__ float wd[2][2][9];

    const int blk = blockIdx.x;
    const int ho  = blk & 127;
    const int g   = (blk >> 7) & 63;
    const int b   = blk >> 13;
    const int wo  = threadIdx.x;
    const int tid = threadIdx.x;

    if (tid < 36) {
        const int o = tid / 18;
        const int c = (tid / 9) & 1;
        const int k = tid % 9;
        wd[o][c][k] = w_deform[(((size_t)(g * 2 + o)) * 2 + c) * 9 + k];
    }

    const size_t CS   = (size_t)HO_ * WO_;
    const __half* cvb = g_conv + (size_t)b * OC_ALL * CS + (size_t)ho * WO_;

    // cooperative stage: 27 channels x 16 chunks of 8 halfs (16 B each)
    for (int i = tid; i < 27 * 16; i += 128) {
        const int j = i >> 4;           // channel slot 0..26
        const int q = i & 15;           // 16B chunk within row
        const int ch = (j < 18) ? (g * 18 + j) : (OC_OFF + g * 9 + (j - 18));
        *reinterpret_cast<uint4*>(&cv[j][q * 8]) =
            *reinterpret_cast<const uint4*>(cvb + (size_t)ch * CS + q * 8);
    }
    __syncthreads();

    const float* xg0 = x + ((size_t)(b * C_ + g * 2) * H_) * W_;
    const float* xg1 = xg0 + (size_t)H_ * W_;

    float acc0 = 0.f, acc1 = 0.f;

#pragma unroll
    for (int k = 0; k < 9; ++k) {
        const float dy = __half2float(cv[2 * k][wo]);
        const float dx = __half2float(cv[2 * k + 1][wo]);
        const float m  = __half2float(cv[18 + k][wo]);

        const int ki = k / 3, kj = k - ki * 3;
        const float py = dy + (float)(2 * ho - 1 + ki);
        const float px = dx + (float)(2 * wo - 1 + kj);

        const float y0f = floorf(py), x0f = floorf(px);
        const float wy = py - y0f, wx = px - x0f;
        const int y0 = (int)y0f, x0 = (int)x0f;
        const int y1 = y0 + 1, x1 = x0 + 1;

        const bool vy0 = (unsigned)y0 < (unsigned)H_;
        const bool vy1 = (unsigned)y1 < (unsigned)H_;
        const bool vx0 = (unsigned)x0 < (unsigned)W_;
        const bool vx1 = (unsigned)x1 < (unsigned)W_;

        const float w00 = (1.f - wy) * (1.f - wx);
        const float w01 = (1.f - wy) * wx;
        const float w10 = wy * (1.f - wx);
        const float w11 = wy * wx;

        const int i00 = y0 * W_ + x0;
        const int i01 = y0 * W_ + x1;
        const int i10 = y1 * W_ + x0;
        const int i11 = y1 * W_ + x1;

        float s0 = 0.f, s1 = 0.f;
        if (vy0 && vx0) { s0 += w00 * xg0[i00]; s1 += w00 * xg1[i00]; }
        if (vy0 && vx1) { s0 += w01 * xg0[i01]; s1 += w01 * xg1[i01]; }
        if (vy1 && vx0) { s0 += w10 * xg0[i10]; s1 += w10 * xg1[i10]; }
        if (vy1 && vx1) { s0 += w11 * xg0[i11]; s1 += w11 * xg1[i11]; }

        s0 *= m; s1 *= m;
        acc0 = fmaf(s0, wd[0][0][k], acc0);
        acc0 = fmaf(s1, wd[0][1][k], acc0);
        acc1 = fmaf(s0, wd[1][0][k], acc1);
        acc1 = fmaf(s1, wd[1][1][k], acc1);
    }

    float* o0 = out + (((size_t)b * C_ + g * 2) * HO_ + ho) * WO_ + wo;
    o0[0]  = acc0;
    o0[CS] = acc1;
}

// ---------------------------------------------------------------------------
extern "C" void kernel_launch(void* const* d_in, const int* in_sizes, int n_in,
                              void* d_out, int out_size)
{
    const float* x        = (const float*)d_in[0];
    const float* w_offset = (const float*)d_in[1];
    const float* b_offset = (const float*)d_in[2];
    const float* w_mask   = (const float*)d_in[3];
    const float* b_mask   = (const float*)d_in[4];
    const float* w_deform = (const float*)d_in[5];
    float* out = (float*)d_out;

    // Stage P+I fused
    prep_kernel<<<I2C_BLOCKS + PACKW_BLOCKS, 256>>>(x, w_offset, w_mask);

    // Stage G
    const int smem = NSTG * STGB;   // 110592 B
    cudaFuncSetAttribute(gemm_f16, cudaFuncAttributeMaxDynamicSharedMemorySize, smem);
    gemm_f16<<<dim3(MPAD / MT, NPIX / NT), 256, smem>>>(b_offset, b_mask);

    // Stage D
    deform_kernel<<<B_ * G_ * HO_, 128>>>(x, w_deform, out);
}